// round 13
// baseline (speedup 1.0000x reference)
#include <cuda_runtime.h>
#include <cuda_bf16.h>
#include <cuda_fp16.h>
#include <cstdint>

#define DIMV 768
#define TTOK 16384
#define HID  3072
#define NQKV 2304

// ---------------- device scratch (allocation-free rule: __device__ globals) -------------
__device__ __align__(256) __half g_act[(size_t)TTOK * DIMV];
__device__ __align__(256) __half g_qkv[(size_t)TTOK * NQKV];
__device__ __align__(256) float  g_y[(size_t)TTOK * DIMV];
__device__ __align__(256) __half g_h[(size_t)TTOK * HID];
__device__ __align__(256) __half g_wqkv[(size_t)NQKV * DIMV];
__device__ __align__(256) __half g_w1[(size_t)HID * DIMV];
__device__ __align__(256) __half g_w2[(size_t)DIMV * HID];
__device__ __align__(256) float  g_qkvb[NQKV];

extern __shared__ char dyn_smem[];

// ---------------- PTX helpers ----------------
__device__ __forceinline__ uint32_t smem_u32(const void* p) {
    uint32_t a;
    asm("{ .reg .u64 t; cvta.to.shared.u64 t, %1; cvt.u32.u64 %0, t; }" : "=r"(a) : "l"(p));
    return a;
}
__device__ __forceinline__ void cp16(uint32_t smaddr, const void* g) {
    asm volatile("cp.async.cg.shared.global [%0], [%1], 16;" :: "r"(smaddr), "l"(g) : "memory");
}
#define CP_COMMIT() asm volatile("cp.async.commit_group;" ::: "memory")
#define CP_WAIT(n)  asm volatile("cp.async.wait_group %0;" :: "n"(n) : "memory")

__device__ __forceinline__ void ldsm_x4(uint32_t* r, uint32_t addr) {
    asm volatile("ldmatrix.sync.aligned.m8n8.x4.shared.b16 {%0,%1,%2,%3}, [%4];"
                 : "=r"(r[0]), "=r"(r[1]), "=r"(r[2]), "=r"(r[3]) : "r"(addr));
}
__device__ __forceinline__ void mma16816h(float* c, const uint32_t* a, const uint32_t* b) {
    asm volatile("mma.sync.aligned.m16n8k16.row.col.f32.f16.f16.f32 "
                 "{%0,%1,%2,%3}, {%4,%5,%6,%7}, {%8,%9}, {%0,%1,%2,%3};"
                 : "+f"(c[0]), "+f"(c[1]), "+f"(c[2]), "+f"(c[3])
                 : "r"(a[0]), "r"(a[1]), "r"(a[2]), "r"(a[3]), "r"(b[0]), "r"(b[1]));
}

// ---------------- small helpers ----------------
__device__ __forceinline__ float warp_sum(float v) {
    #pragma unroll
    for (int o = 16; o > 0; o >>= 1) v += __shfl_xor_sync(0xffffffffu, v, o);
    return v;
}

// ---------------- prep kernels ----------------
__global__ void prep_qkv(const float* __restrict__ wq, const float* __restrict__ wk,
                         const float* __restrict__ wv, const float* __restrict__ bq,
                         const float* __restrict__ bk, const float* __restrict__ bv) {
    const int n = DIMV * DIMV;
    for (int i = blockIdx.x * blockDim.x + threadIdx.x; i < 3 * n + NQKV; i += gridDim.x * blockDim.x) {
        if (i < 3 * n) {
            int s = i / n, j = i - s * n;
            const float* w = (s == 0) ? wq : (s == 1) ? wk : wv;
            g_wqkv[(size_t)s * n + j] = __float2half(w[j]);
        } else {
            int j = i - 3 * n;
            g_qkvb[j] = (j < 768) ? bq[j] : (j < 1536) ? bk[j - 768] : bv[j - 1536];
        }
    }
}
__global__ void prep_mlp(const float* __restrict__ d1, const float* __restrict__ d2) {
    const int n = HID * DIMV;
    for (int i = blockIdx.x * blockDim.x + threadIdx.x; i < 2 * n; i += gridDim.x * blockDim.x) {
        if (i < n) g_w1[i] = __float2half(d1[i]);
        else       g_w2[i - n] = __float2half(d2[i - n]);
    }
}

// ---------------- LN1: x -> fp16(layernorm(x)) ; warp per token ----------------
__global__ void ln1_kernel(const float* __restrict__ x, const float* __restrict__ g1,
                           const float* __restrict__ b1) {
    int wid = threadIdx.x >> 5, lid = threadIdx.x & 31;
    int tok = blockIdx.x * 8 + wid;
    const float* xr = x + (size_t)tok * DIMV;
    float xv[24];
    #pragma unroll
    for (int j = 0; j < 24; ++j) xv[j] = xr[lid + 32 * j];
    float s = 0.f;
    #pragma unroll
    for (int j = 0; j < 24; ++j) s += xv[j];
    float mean = warp_sum(s) * (1.0f / DIMV);
    float s2 = 0.f;
    #pragma unroll
    for (int j = 0; j < 24; ++j) { float d = xv[j] - mean; s2 += d * d; }
    float var = warp_sum(s2) * (1.0f / (DIMV - 1));
    float inv = g1[0] / (sqrtf(var) + 1e-6f);
    float bb = b1[0];
    size_t base = (size_t)tok * DIMV;
    #pragma unroll
    for (int j = 0; j < 24; ++j)
        g_act[base + lid + 32 * j] = __float2half((xv[j] - mean) * inv + bb);
}

// ---------------- attention + residual + LN2 (q/k/v in fp16) ----------------
__global__ void attn_ln2_kernel(const float* __restrict__ x, const float* __restrict__ g2,
                                const float* __restrict__ b2) {
    float* ks = (float*)dyn_smem;
    float* vs = ks + 8 * DIMV;
    int tid = threadIdx.x;
    int wid = tid >> 5, lid = tid & 31;
    int t0 = blockIdx.x * 8;
    for (int i = tid; i < 8 * DIMV; i += 256) {
        int r = i / DIMV, c = i - r * DIMV;
        const __half* row = g_qkv + (size_t)(t0 + r) * NQKV;
        ks[i] = __half2float(row[768 + c]);
        vs[i] = __half2float(row[1536 + c]);
    }
    __syncthreads();
    int h = wid;
    const __half* qr = g_qkv + (size_t)(t0 + h) * NQKV;
    float qv[24];
    #pragma unroll
    for (int j = 0; j < 24; ++j) qv[j] = __half2float(qr[lid + 32 * j]);
    float p[8];
    #pragma unroll
    for (int kk = 0; kk < 8; ++kk) {
        float acc = 0.f;
        const float* kr = ks + kk * DIMV;
        #pragma unroll
        for (int j = 0; j < 24; ++j) acc += qv[j] * kr[lid + 32 * j];
        p[kk] = acc;
    }
    #pragma unroll
    for (int kk = 0; kk < 8; ++kk) p[kk] = warp_sum(p[kk]) * 0.03608439182435161f;
    float m = p[0];
    #pragma unroll
    for (int kk = 1; kk < 8; ++kk) m = fmaxf(m, p[kk]);
    float se = 0.f;
    #pragma unroll
    for (int kk = 0; kk < 8; ++kk) { p[kk] = __expf(p[kk] - m); se += p[kk]; }
    float rinv = 1.0f / se;
    #pragma unroll
    for (int kk = 0; kk < 8; ++kk) p[kk] *= rinv;
    const float* xr = x + (size_t)(t0 + h) * DIMV;
    float yv[24];
    #pragma unroll
    for (int j = 0; j < 24; ++j) {
        int d = lid + 32 * j;
        float a = 0.f;
        #pragma unroll
        for (int kk = 0; kk < 8; ++kk) a += p[kk] * vs[kk * DIMV + d];
        yv[j] = a + xr[d];
    }
    size_t base = (size_t)(t0 + h) * DIMV;
    #pragma unroll
    for (int j = 0; j < 24; ++j) g_y[base + lid + 32 * j] = yv[j];
    float s = 0.f;
    #pragma unroll
    for (int j = 0; j < 24; ++j) s += yv[j];
    float mean = warp_sum(s) * (1.0f / DIMV);
    float s2 = 0.f;
    #pragma unroll
    for (int j = 0; j < 24; ++j) { float d = yv[j] - mean; s2 += d * d; }
    float var = warp_sum(s2) * (1.0f / (DIMV - 1));
    float inv = g2[0] / (sqrtf(var) + 1e-6f);
    float bb = b2[0];
    #pragma unroll
    for (int j = 0; j < 24; ++j)
        g_act[base + lid + 32 * j] = __float2half((yv[j] - mean) * inv + bb);
}

// ---------------- fp16 GEMM: 128x128 tile, BK=64, 16 warps (4x4, warp 32x32), 2 CTAs/SM -
// R11 structure + per-warp ks-phase rotation (warps start at ks=(wid&3) to interleave
// ldsm and MMA phases across the SMSP instead of convoying after each barrier).
#define PITCH   144
#define ST_A    18432
#define ST_SIZE 36864
#define N_STAGE 3
#define GEMM_SMEM (N_STAGE * ST_SIZE)

// EPI 0: act @ wqkv^T + qkvb  -> g_qkv (fp16)   (K=768,  N=2304)
// EPI 1: act @ w1^T + d1_b, gelu -> g_h (fp16)  (K=768,  N=3072)
// EPI 2: h @ w2^T + d2_b + g_y -> outF          (K=3072, N=768)
template <int EPI>
__global__ void __launch_bounds__(512, 2) gemm_k(const float* __restrict__ bias, float* __restrict__ outF) {
    constexpr int Kd = (EPI == 2) ? HID : DIMV;
    constexpr int NCH = Kd / 64;
    const __half* A = (EPI == 2) ? g_h : g_act;
    const __half* B = (EPI == 0) ? g_wqkv : (EPI == 1) ? g_w1 : g_w2;

    const int tid = threadIdx.x;
    const int lane = tid & 31, wid = tid >> 5;
    const int wm = wid >> 2, wn = wid & 3;      // 4 x 4 warp grid; warp tile 32 x 32
    const int bx = blockIdx.x, by = blockIdx.y;
    const uint32_t smb = smem_u32(dyn_smem);

    const uint32_t a_off = (uint32_t)(wm * 32 + (lane & 15)) * PITCH + (lane >> 4) * 16;
    const int g = lane >> 3;
    const uint32_t b_off = ST_A + (uint32_t)(wn * 32 + (g >> 1) * 8 + (lane & 7)) * PITCH + (g & 1) * 16;

    // per-warp rotated ks byte offsets: warp w starts at ks = w & 3
    uint32_t koff[4];
    #pragma unroll
    for (int kk = 0; kk < 4; ++kk) koff[kk] = (uint32_t)(((kk + wid) & 3) * 32);

    auto load_stage = [&](int c, int st) {
        uint32_t sb = smb + st * ST_SIZE;
        #pragma unroll
        for (int j = 0; j < 2; ++j) {
            int id = tid + 512 * j;
            int r = id >> 3, q = id & 7;
            cp16(sb + r * PITCH + q * 16, A + (size_t)(by * 128 + r) * Kd + c * 64 + q * 8);
        }
        #pragma unroll
        for (int j = 0; j < 2; ++j) {
            int id = tid + 512 * j;
            int r = id >> 3, q = id & 7;
            cp16(sb + ST_A + r * PITCH + q * 16, B + (size_t)(bx * 128 + r) * Kd + c * 64 + q * 8);
        }
        CP_COMMIT();
    };

    float acc[2][4][4];
    #pragma unroll
    for (int mi = 0; mi < 2; ++mi)
        #pragma unroll
        for (int ni = 0; ni < 4; ++ni)
            #pragma unroll
            for (int r = 0; r < 4; ++r) acc[mi][ni][r] = 0.f;

    load_stage(0, 0);
    load_stage(1, 1);

    for (int c = 0; c < NCH; ++c) {
        CP_WAIT(1);                              // group c complete
        __syncthreads();                         // stage c visible; buf (c+2)%3 free
        if (c + 2 < NCH) load_stage(c + 2, (c + 2) % N_STAGE);

        const uint32_t sb = smb + (c % N_STAGE) * ST_SIZE;
        #pragma unroll
        for (int kk = 0; kk < 4; ++kk) {
            const uint32_t ko = koff[kk];
            // B frags: 2 ldsm_x4, each covers 2 adjacent ni
            uint32_t bf[4][2];
            #pragma unroll
            for (int nb = 0; nb < 2; ++nb) {
                uint32_t t[4];
                ldsm_x4(t, sb + b_off + nb * (16 * PITCH) + ko);
                bf[2 * nb][0] = t[0]; bf[2 * nb][1] = t[1];
                bf[2 * nb + 1][0] = t[2]; bf[2 * nb + 1][1] = t[3];
            }
            #pragma unroll
            for (int mi = 0; mi < 2; ++mi) {
                uint32_t a[4];
                ldsm_x4(a, sb + a_off + mi * (16 * PITCH) + ko);
                #pragma unroll
                for (int ni = 0; ni < 4; ++ni)
                    mma16816h(acc[mi][ni], a, bf[ni]);
            }
        }
    }

    // ---------------- epilogue ----------------
    const int r0 = lane >> 2, c0 = 2 * (lane & 3);
    #pragma unroll
    for (int mi = 0; mi < 2; ++mi) {
        #pragma unroll
        for (int hh = 0; hh < 2; ++hh) {
            const int grow = by * 128 + wm * 32 + mi * 16 + r0 + hh * 8;
            #pragma unroll
            for (int ni = 0; ni < 4; ++ni) {
                const int gcol = bx * 128 + wn * 32 + ni * 8 + c0;
                float v0 = acc[mi][ni][2 * hh + 0];
                float v1 = acc[mi][ni][2 * hh + 1];
                if (EPI == 0) {
                    size_t idx = (size_t)grow * NQKV + gcol;
                    *(__half2*)(g_qkv + idx) =
                        __half2(__float2half(v0 + g_qkvb[gcol]), __float2half(v1 + g_qkvb[gcol + 1]));
                } else if (EPI == 1) {
                    float u0 = v0 + bias[gcol];
                    float u1 = v1 + bias[gcol + 1];
                    float gl0 = 0.5f * u0 * (1.0f + erff(u0 * 0.70710678118654752440f));
                    float gl1 = 0.5f * u1 * (1.0f + erff(u1 * 0.70710678118654752440f));
                    size_t idx = (size_t)grow * HID + gcol;
                    *(__half2*)(g_h + idx) = __half2(__float2half(gl0), __float2half(gl1));
                } else {
                    size_t idx = (size_t)grow * DIMV + gcol;
                    float2 res = *(const float2*)(g_y + idx);
                    float2 o;
                    o.x = v0 + bias[gcol] + res.x;
                    o.y = v1 + bias[gcol + 1] + res.y;
                    *(float2*)(outF + idx) = o;
                }
            }
        }
    }
}

// ---------------- launch ----------------
#define ATTN_SMEM (2 * 8 * DIMV * (int)sizeof(float))

extern "C" void kernel_launch(void* const* d_in, const int* in_sizes, int n_in,
                              void* d_out, int out_size) {
    const float* x    = (const float*)d_in[0];
    const float* wq_w = (const float*)d_in[1];
    const float* wq_b = (const float*)d_in[2];
    const float* wk_w = (const float*)d_in[3];
    const float* wk_b = (const float*)d_in[4];
    const float* wv_w = (const float*)d_in[5];
    const float* wv_b = (const float*)d_in[6];
    const float* d1_w = (const float*)d_in[7];
    const float* d1_b = (const float*)d_in[8];
    const float* d2_w = (const float*)d_in[9];
    const float* d2_b = (const float*)d_in[10];
    const float* g1   = (const float*)d_in[11];
    const float* b1   = (const float*)d_in[12];
    const float* g2   = (const float*)d_in[13];
    const float* b2   = (const float*)d_in[14];
    float* out = (float*)d_out;

    cudaFuncSetAttribute(gemm_k<0>, cudaFuncAttributeMaxDynamicSharedMemorySize, GEMM_SMEM);
    cudaFuncSetAttribute(gemm_k<1>, cudaFuncAttributeMaxDynamicSharedMemorySize, GEMM_SMEM);
    cudaFuncSetAttribute(gemm_k<2>, cudaFuncAttributeMaxDynamicSharedMemorySize, GEMM_SMEM);
    cudaFuncSetAttribute(attn_ln2_kernel, cudaFuncAttributeMaxDynamicSharedMemorySize, ATTN_SMEM);

    prep_qkv<<<2048, 256>>>(wq_w, wk_w, wv_w, wq_b, wk_b, wv_b);       // 0
    prep_mlp<<<4096, 256>>>(d1_w, d2_w);                               // 1
    ln1_kernel<<<TTOK / 8, 256>>>(x, g1, b1);                          // 2
    gemm_k<0><<<dim3(NQKV / 128, TTOK / 128), 512, GEMM_SMEM>>>(nullptr, nullptr);  // 3
    attn_ln2_kernel<<<TTOK / 8, 256, ATTN_SMEM>>>(x, g2, b2);          // 4
    gemm_k<1><<<dim3(HID / 128, TTOK / 128), 512, GEMM_SMEM>>>(d1_b, nullptr);      // 5
    gemm_k<2><<<dim3(DIMV / 128, TTOK / 128), 512, GEMM_SMEM>>>(d2_b, out);         // 6
}

// round 14
// speedup vs baseline: 1.1839x; 1.1839x over previous
#include <cuda_runtime.h>
#include <cuda_bf16.h>
#include <cuda_fp16.h>
#include <cstdint>

#define DIMV 768
#define TTOK 16384
#define HID  3072
#define NQKV 2304

// ---------------- device scratch (allocation-free rule: __device__ globals) -------------
__device__ __align__(256) __half g_act[(size_t)TTOK * DIMV];
__device__ __align__(256) __half g_qkv[(size_t)TTOK * NQKV];
__device__ __align__(256) float  g_y[(size_t)TTOK * DIMV];
__device__ __align__(256) __half g_h[(size_t)TTOK * HID];
__device__ __align__(256) __half g_wqkv[(size_t)NQKV * DIMV];
__device__ __align__(256) __half g_w1[(size_t)HID * DIMV];
__device__ __align__(256) __half g_w2[(size_t)DIMV * HID];
__device__ __align__(256) float  g_qkvb[NQKV];

extern __shared__ char dyn_smem[];

// ---------------- PTX helpers ----------------
__device__ __forceinline__ uint32_t smem_u32(const void* p) {
    uint32_t a;
    asm("{ .reg .u64 t; cvta.to.shared.u64 t, %1; cvt.u32.u64 %0, t; }" : "=r"(a) : "l"(p));
    return a;
}
__device__ __forceinline__ void cp16(uint32_t smaddr, const void* g) {
    asm volatile("cp.async.cg.shared.global [%0], [%1], 16;" :: "r"(smaddr), "l"(g) : "memory");
}
#define CP_COMMIT() asm volatile("cp.async.commit_group;" ::: "memory")
#define CP_WAIT(n)  asm volatile("cp.async.wait_group %0;" :: "n"(n) : "memory")

__device__ __forceinline__ void ldsm_x4(uint32_t* r, uint32_t addr) {
    asm volatile("ldmatrix.sync.aligned.m8n8.x4.shared.b16 {%0,%1,%2,%3}, [%4];"
                 : "=r"(r[0]), "=r"(r[1]), "=r"(r[2]), "=r"(r[3]) : "r"(addr));
}
__device__ __forceinline__ void mma16816h(float* c, const uint32_t* a, const uint32_t* b) {
    asm volatile("mma.sync.aligned.m16n8k16.row.col.f32.f16.f16.f32 "
                 "{%0,%1,%2,%3}, {%4,%5,%6,%7}, {%8,%9}, {%0,%1,%2,%3};"
                 : "+f"(c[0]), "+f"(c[1]), "+f"(c[2]), "+f"(c[3])
                 : "r"(a[0]), "r"(a[1]), "r"(a[2]), "r"(a[3]), "r"(b[0]), "r"(b[1]));
}

// ---------------- small helpers ----------------
__device__ __forceinline__ float warp_sum(float v) {
    #pragma unroll
    for (int o = 16; o > 0; o >>= 1) v += __shfl_xor_sync(0xffffffffu, v, o);
    return v;
}

// ---------------- merged prep: all weight fp16 conversions + bias concat ----------------
__global__ void prep_all(const float* __restrict__ wq, const float* __restrict__ wk,
                         const float* __restrict__ wv, const float* __restrict__ bq,
                         const float* __restrict__ bk, const float* __restrict__ bv,
                         const float* __restrict__ d1, const float* __restrict__ d2) {
    const int n = DIMV * DIMV;       // 589824
    const int m = HID * DIMV;        // 2359296
    const int t0 = 3 * n;            // qkv weights end
    const int t1 = t0 + NQKV;        // bias end
    const int t2 = t1 + m;           // w1 end
    const int total = t2 + m;
    for (int i = blockIdx.x * blockDim.x + threadIdx.x; i < total; i += gridDim.x * blockDim.x) {
        if (i < t0) {
            int s = i / n, j = i - s * n;
            const float* w = (s == 0) ? wq : (s == 1) ? wk : wv;
            g_wqkv[(size_t)s * n + j] = __float2half(w[j]);
        } else if (i < t1) {
            int j = i - t0;
            g_qkvb[j] = (j < 768) ? bq[j] : (j < 1536) ? bk[j - 768] : bv[j - 1536];
        } else if (i < t2) {
            int j = i - t1;
            g_w1[j] = __float2half(d1[j]);
        } else {
            int j = i - t2;
            g_w2[j] = __float2half(d2[j]);
        }
    }
}

// ---------------- LN1 (vectorized float2/half2): x -> fp16(layernorm(x)) ----------------
__global__ void ln1_kernel(const float* __restrict__ x, const float* __restrict__ g1,
                           const float* __restrict__ b1) {
    int wid = threadIdx.x >> 5, lid = threadIdx.x & 31;
    int tok = blockIdx.x * 8 + wid;
    const float2* xr = (const float2*)(x + (size_t)tok * DIMV);
    float2 xv[12];
    #pragma unroll
    for (int j = 0; j < 12; ++j) xv[j] = xr[lid + 32 * j];
    float s = 0.f;
    #pragma unroll
    for (int j = 0; j < 12; ++j) s += xv[j].x + xv[j].y;
    float mean = warp_sum(s) * (1.0f / DIMV);
    float s2 = 0.f;
    #pragma unroll
    for (int j = 0; j < 12; ++j) {
        float dx = xv[j].x - mean, dy = xv[j].y - mean;
        s2 += dx * dx + dy * dy;
    }
    float var = warp_sum(s2) * (1.0f / (DIMV - 1));
    float inv = g1[0] / (sqrtf(var) + 1e-6f);
    float bb = b1[0];
    __half2* ar = (__half2*)(g_act + (size_t)tok * DIMV);
    #pragma unroll
    for (int j = 0; j < 12; ++j)
        ar[lid + 32 * j] = __floats2half2_rn((xv[j].x - mean) * inv + bb,
                                             (xv[j].y - mean) * inv + bb);
}

// ---------------- attention + residual + LN2 (vectorized) ----------------
// smem: ks2/vs2 as float2[8*384] each
__global__ void attn_ln2_kernel(const float* __restrict__ x, const float* __restrict__ g2,
                                const float* __restrict__ b2) {
    float2* ks2 = (float2*)dyn_smem;          // 8 * 384
    float2* vs2 = ks2 + 8 * 384;
    int tid = threadIdx.x;
    int wid = tid >> 5, lid = tid & 31;
    int t0 = blockIdx.x * 8;
    // load k,v (half2) -> smem float2 ; 3072 half2 per tensor
    for (int i = tid; i < 8 * 384; i += 256) {
        int r = i / 384, c = i - r * 384;
        const __half2* row = (const __half2*)(g_qkv + (size_t)(t0 + r) * NQKV);
        ks2[i] = __half22float2(row[384 + c]);
        vs2[i] = __half22float2(row[768 + c]);
    }
    __syncthreads();
    int h = wid;
    const __half2* qr = (const __half2*)(g_qkv + (size_t)(t0 + h) * NQKV);
    float2 qv[12];
    #pragma unroll
    for (int j = 0; j < 12; ++j) qv[j] = __half22float2(qr[lid + 32 * j]);
    float p[8];
    #pragma unroll
    for (int kk = 0; kk < 8; ++kk) {
        float acc = 0.f;
        const float2* kr = ks2 + kk * 384;
        #pragma unroll
        for (int j = 0; j < 12; ++j) {
            float2 k2 = kr[lid + 32 * j];
            acc += qv[j].x * k2.x + qv[j].y * k2.y;
        }
        p[kk] = acc;
    }
    #pragma unroll
    for (int kk = 0; kk < 8; ++kk) p[kk] = warp_sum(p[kk]) * 0.03608439182435161f;
    float m = p[0];
    #pragma unroll
    for (int kk = 1; kk < 8; ++kk) m = fmaxf(m, p[kk]);
    float se = 0.f;
    #pragma unroll
    for (int kk = 0; kk < 8; ++kk) { p[kk] = __expf(p[kk] - m); se += p[kk]; }
    float rinv = 1.0f / se;
    #pragma unroll
    for (int kk = 0; kk < 8; ++kk) p[kk] *= rinv;
    const float2* xr = (const float2*)(x + (size_t)(t0 + h) * DIMV);
    float2* yr = (float2*)(g_y + (size_t)(t0 + h) * DIMV);
    float2 yv[12];
    #pragma unroll
    for (int j = 0; j < 12; ++j) {
        int d = lid + 32 * j;
        float ax = 0.f, ay = 0.f;
        #pragma unroll
        for (int kk = 0; kk < 8; ++kk) {
            float2 v2 = vs2[kk * 384 + d];
            ax += p[kk] * v2.x;
            ay += p[kk] * v2.y;
        }
        float2 x2 = xr[d];
        yv[j].x = ax + x2.x;
        yv[j].y = ay + x2.y;
        yr[d] = yv[j];
    }
    float s = 0.f;
    #pragma unroll
    for (int j = 0; j < 12; ++j) s += yv[j].x + yv[j].y;
    float mean = warp_sum(s) * (1.0f / DIMV);
    float s2 = 0.f;
    #pragma unroll
    for (int j = 0; j < 12; ++j) {
        float dx = yv[j].x - mean, dy = yv[j].y - mean;
        s2 += dx * dx + dy * dy;
    }
    float var = warp_sum(s2) * (1.0f / (DIMV - 1));
    float inv = g2[0] / (sqrtf(var) + 1e-6f);
    float bb = b2[0];
    __half2* ar = (__half2*)(g_act + (size_t)(t0 + h) * DIMV);
    #pragma unroll
    for (int j = 0; j < 12; ++j)
        ar[lid + 32 * j] = __floats2half2_rn((yv[j].x - mean) * inv + bb,
                                             (yv[j].y - mean) * inv + bb);
}

// ---------------- fp16 GEMM: 128x128 tile, BK=64, 16 warps (4x4, warp 32x32), 2 CTAs/SM -
// (R11-proven structure: CP_WAIT(1), prefetch distance 2, 3 stages, 64 regs — DO NOT PERTURB)
#define PITCH   144
#define ST_A    18432
#define ST_SIZE 36864
#define N_STAGE 3
#define GEMM_SMEM (N_STAGE * ST_SIZE)

// EPI 0: act @ wqkv^T + qkvb  -> g_qkv (fp16)   (K=768,  N=2304)
// EPI 1: act @ w1^T + d1_b, gelu -> g_h (fp16)  (K=768,  N=3072)
// EPI 2: h @ w2^T + d2_b + g_y -> outF          (K=3072, N=768)
template <int EPI>
__global__ void __launch_bounds__(512, 2) gemm_k(const float* __restrict__ bias, float* __restrict__ outF) {
    constexpr int Kd = (EPI == 2) ? HID : DIMV;
    constexpr int NCH = Kd / 64;
    const __half* A = (EPI == 2) ? g_h : g_act;
    const __half* B = (EPI == 0) ? g_wqkv : (EPI == 1) ? g_w1 : g_w2;

    const int tid = threadIdx.x;
    const int lane = tid & 31, wid = tid >> 5;
    const int wm = wid >> 2, wn = wid & 3;      // 4 x 4 warp grid; warp tile 32 x 32
    const int bx = blockIdx.x, by = blockIdx.y;
    const uint32_t smb = smem_u32(dyn_smem);

    const uint32_t a_off = (uint32_t)(wm * 32 + (lane & 15)) * PITCH + (lane >> 4) * 16;
    const int g = lane >> 3;
    const uint32_t b_off = ST_A + (uint32_t)(wn * 32 + (g >> 1) * 8 + (lane & 7)) * PITCH + (g & 1) * 16;

    auto load_stage = [&](int c, int st) {
        uint32_t sb = smb + st * ST_SIZE;
        #pragma unroll
        for (int j = 0; j < 2; ++j) {
            int id = tid + 512 * j;
            int r = id >> 3, q = id & 7;
            cp16(sb + r * PITCH + q * 16, A + (size_t)(by * 128 + r) * Kd + c * 64 + q * 8);
        }
        #pragma unroll
        for (int j = 0; j < 2; ++j) {
            int id = tid + 512 * j;
            int r = id >> 3, q = id & 7;
            cp16(sb + ST_A + r * PITCH + q * 16, B + (size_t)(bx * 128 + r) * Kd + c * 64 + q * 8);
        }
        CP_COMMIT();
    };

    float acc[2][4][4];
    #pragma unroll
    for (int mi = 0; mi < 2; ++mi)
        #pragma unroll
        for (int ni = 0; ni < 4; ++ni)
            #pragma unroll
            for (int r = 0; r < 4; ++r) acc[mi][ni][r] = 0.f;

    load_stage(0, 0);
    load_stage(1, 1);

    for (int c = 0; c < NCH; ++c) {
        CP_WAIT(1);                              // group c complete
        __syncthreads();                         // stage c visible; buf (c+2)%3 free
        if (c + 2 < NCH) load_stage(c + 2, (c + 2) % N_STAGE);

        const uint32_t sb = smb + (c % N_STAGE) * ST_SIZE;
        #pragma unroll
        for (int ks = 0; ks < 4; ++ks) {
            uint32_t bf[4][2];
            #pragma unroll
            for (int nb = 0; nb < 2; ++nb) {
                uint32_t t[4];
                ldsm_x4(t, sb + b_off + nb * (16 * PITCH) + ks * 32);
                bf[2 * nb][0] = t[0]; bf[2 * nb][1] = t[1];
                bf[2 * nb + 1][0] = t[2]; bf[2 * nb + 1][1] = t[3];
            }
            #pragma unroll
            for (int mi = 0; mi < 2; ++mi) {
                uint32_t a[4];
                ldsm_x4(a, sb + a_off + mi * (16 * PITCH) + ks * 32);
                #pragma unroll
                for (int ni = 0; ni < 4; ++ni)
                    mma16816h(acc[mi][ni], a, bf[ni]);
            }
        }
    }

    // ---------------- epilogue ----------------
    const int r0 = lane >> 2, c0 = 2 * (lane & 3);
    #pragma unroll
    for (int mi = 0; mi < 2; ++mi) {
        #pragma unroll
        for (int hh = 0; hh < 2; ++hh) {
            const int grow = by * 128 + wm * 32 + mi * 16 + r0 + hh * 8;
            #pragma unroll
            for (int ni = 0; ni < 4; ++ni) {
                const int gcol = bx * 128 + wn * 32 + ni * 8 + c0;
                float v0 = acc[mi][ni][2 * hh + 0];
                float v1 = acc[mi][ni][2 * hh + 1];
                if (EPI == 0) {
                    size_t idx = (size_t)grow * NQKV + gcol;
                    *(__half2*)(g_qkv + idx) =
                        __half2(__float2half(v0 + g_qkvb[gcol]), __float2half(v1 + g_qkvb[gcol + 1]));
                } else if (EPI == 1) {
                    float u0 = v0 + bias[gcol];
                    float u1 = v1 + bias[gcol + 1];
                    float gl0 = 0.5f * u0 * (1.0f + erff(u0 * 0.70710678118654752440f));
                    float gl1 = 0.5f * u1 * (1.0f + erff(u1 * 0.70710678118654752440f));
                    size_t idx = (size_t)grow * HID + gcol;
                    *(__half2*)(g_h + idx) = __half2(__float2half(gl0), __float2half(gl1));
                } else {
                    size_t idx = (size_t)grow * DIMV + gcol;
                    float2 res = *(const float2*)(g_y + idx);
                    float2 o;
                    o.x = v0 + bias[gcol] + res.x;
                    o.y = v1 + bias[gcol + 1] + res.y;
                    *(float2*)(outF + idx) = o;
                }
            }
        }
    }
}

// ---------------- launch ----------------
#define ATTN_SMEM (2 * 8 * DIMV * (int)sizeof(float))

extern "C" void kernel_launch(void* const* d_in, const int* in_sizes, int n_in,
                              void* d_out, int out_size) {
    const float* x    = (const float*)d_in[0];
    const float* wq_w = (const float*)d_in[1];
    const float* wq_b = (const float*)d_in[2];
    const float* wk_w = (const float*)d_in[3];
    const float* wk_b = (const float*)d_in[4];
    const float* wv_w = (const float*)d_in[5];
    const float* wv_b = (const float*)d_in[6];
    const float* d1_w = (const float*)d_in[7];
    const float* d1_b = (const float*)d_in[8];
    const float* d2_w = (const float*)d_in[9];
    const float* d2_b = (const float*)d_in[10];
    const float* g1   = (const float*)d_in[11];
    const float* b1   = (const float*)d_in[12];
    const float* g2   = (const float*)d_in[13];
    const float* b2   = (const float*)d_in[14];
    float* out = (float*)d_out;

    cudaFuncSetAttribute(gemm_k<0>, cudaFuncAttributeMaxDynamicSharedMemorySize, GEMM_SMEM);
    cudaFuncSetAttribute(gemm_k<1>, cudaFuncAttributeMaxDynamicSharedMemorySize, GEMM_SMEM);
    cudaFuncSetAttribute(gemm_k<2>, cudaFuncAttributeMaxDynamicSharedMemorySize, GEMM_SMEM);
    cudaFuncSetAttribute(attn_ln2_kernel, cudaFuncAttributeMaxDynamicSharedMemorySize, ATTN_SMEM);

    prep_all<<<4096, 256>>>(wq_w, wk_w, wv_w, wq_b, wk_b, wv_b, d1_w, d2_w);        // 0
    ln1_kernel<<<TTOK / 8, 256>>>(x, g1, b1);                                       // 1
    gemm_k<0><<<dim3(NQKV / 128, TTOK / 128), 512, GEMM_SMEM>>>(nullptr, nullptr);  // 2
    attn_ln2_kernel<<<TTOK / 8, 256, ATTN_SMEM>>>(x, g2, b2);                       // 3
    gemm_k<1><<<dim3(HID / 128, TTOK / 128), 512, GEMM_SMEM>>>(d1_b, nullptr);      // 4
    gemm_k<2><<<dim3(DIMV / 128, TTOK / 128), 512, GEMM_SMEM>>>(d2_b, out);         // 5 <- profiled
}

// round 15
// speedup vs baseline: 1.2049x; 1.0178x over previous
#include <cuda_runtime.h>
#include <cuda_bf16.h>
#include <cuda_fp16.h>
#include <cstdint>

#define DIMV 768
#define TTOK 16384
#define HID  3072
#define NQKV 2304

// ---------------- device scratch (allocation-free rule: __device__ globals) -------------
__device__ __align__(256) __half g_act[(size_t)TTOK * DIMV];
__device__ __align__(256) __half g_qkv[(size_t)TTOK * NQKV];
__device__ __align__(256) __half g_y[(size_t)TTOK * DIMV];
__device__ __align__(256) __half g_h[(size_t)TTOK * HID];
__device__ __align__(256) __half g_wqkv[(size_t)NQKV * DIMV];
__device__ __align__(256) __half g_w1[(size_t)HID * DIMV];
__device__ __align__(256) __half g_w2[(size_t)DIMV * HID];
__device__ __align__(256) float  g_qkvb[NQKV];

extern __shared__ char dyn_smem[];

// ---------------- PTX helpers ----------------
__device__ __forceinline__ uint32_t smem_u32(const void* p) {
    uint32_t a;
    asm("{ .reg .u64 t; cvta.to.shared.u64 t, %1; cvt.u32.u64 %0, t; }" : "=r"(a) : "l"(p));
    return a;
}
__device__ __forceinline__ void cp16(uint32_t smaddr, const void* g) {
    asm volatile("cp.async.cg.shared.global [%0], [%1], 16;" :: "r"(smaddr), "l"(g) : "memory");
}
#define CP_COMMIT() asm volatile("cp.async.commit_group;" ::: "memory")
#define CP_WAIT(n)  asm volatile("cp.async.wait_group %0;" :: "n"(n) : "memory")

__device__ __forceinline__ void ldsm_x4(uint32_t* r, uint32_t addr) {
    asm volatile("ldmatrix.sync.aligned.m8n8.x4.shared.b16 {%0,%1,%2,%3}, [%4];"
                 : "=r"(r[0]), "=r"(r[1]), "=r"(r[2]), "=r"(r[3]) : "r"(addr));
}
__device__ __forceinline__ void mma16816h(float* c, const uint32_t* a, const uint32_t* b) {
    asm volatile("mma.sync.aligned.m16n8k16.row.col.f32.f16.f16.f32 "
                 "{%0,%1,%2,%3}, {%4,%5,%6,%7}, {%8,%9}, {%0,%1,%2,%3};"
                 : "+f"(c[0]), "+f"(c[1]), "+f"(c[2]), "+f"(c[3])
                 : "r"(a[0]), "r"(a[1]), "r"(a[2]), "r"(a[3]), "r"(b[0]), "r"(b[1]));
}

// ---------------- small helpers ----------------
__device__ __forceinline__ float warp_sum(float v) {
    #pragma unroll
    for (int o = 16; o > 0; o >>= 1) v += __shfl_xor_sync(0xffffffffu, v, o);
    return v;
}

// ---------------- merged prep: all weight fp16 conversions + bias concat ----------------
__global__ void prep_all(const float* __restrict__ wq, const float* __restrict__ wk,
                         const float* __restrict__ wv, const float* __restrict__ bq,
                         const float* __restrict__ bk, const float* __restrict__ bv,
                         const float* __restrict__ d1, const float* __restrict__ d2) {
    const int n = DIMV * DIMV;
    const int m = HID * DIMV;
    const int t0 = 3 * n;
    const int t1 = t0 + NQKV;
    const int t2 = t1 + m;
    const int total = t2 + m;
    for (int i = blockIdx.x * blockDim.x + threadIdx.x; i < total; i += gridDim.x * blockDim.x) {
        if (i < t0) {
            int s = i / n, j = i - s * n;
            const float* w = (s == 0) ? wq : (s == 1) ? wk : wv;
            g_wqkv[(size_t)s * n + j] = __float2half(w[j]);
        } else if (i < t1) {
            int j = i - t0;
            g_qkvb[j] = (j < 768) ? bq[j] : (j < 1536) ? bk[j - 768] : bv[j - 1536];
        } else if (i < t2) {
            int j = i - t1;
            g_w1[j] = __float2half(d1[j]);
        } else {
            int j = i - t2;
            g_w2[j] = __float2half(d2[j]);
        }
    }
}

// ---------------- LN1 (vectorized float2/half2): x -> fp16(layernorm(x)) ----------------
__global__ void ln1_kernel(const float* __restrict__ x, const float* __restrict__ g1,
                           const float* __restrict__ b1) {
    int wid = threadIdx.x >> 5, lid = threadIdx.x & 31;
    int tok = blockIdx.x * 8 + wid;
    const float2* xr = (const float2*)(x + (size_t)tok * DIMV);
    float2 xv[12];
    #pragma unroll
    for (int j = 0; j < 12; ++j) xv[j] = xr[lid + 32 * j];
    float s = 0.f;
    #pragma unroll
    for (int j = 0; j < 12; ++j) s += xv[j].x + xv[j].y;
    float mean = warp_sum(s) * (1.0f / DIMV);
    float s2 = 0.f;
    #pragma unroll
    for (int j = 0; j < 12; ++j) {
        float dx = xv[j].x - mean, dy = xv[j].y - mean;
        s2 += dx * dx + dy * dy;
    }
    float var = warp_sum(s2) * (1.0f / (DIMV - 1));
    float inv = g1[0] / (sqrtf(var) + 1e-6f);
    float bb = b1[0];
    __half2* ar = (__half2*)(g_act + (size_t)tok * DIMV);
    #pragma unroll
    for (int j = 0; j < 12; ++j)
        ar[lid + 32 * j] = __floats2half2_rn((xv[j].x - mean) * inv + bb,
                                             (xv[j].y - mean) * inv + bb);
}

// ---------------- attention + residual + LN2 (k/v kept fp16 in smem; y stored fp16) -----
// smem: ks2/vs2 as __half2[8*384] each => 24576 B total -> 8 blocks/SM
__global__ void attn_ln2_kernel(const float* __restrict__ x, const float* __restrict__ g2,
                                const float* __restrict__ b2) {
    __half2* ks2 = (__half2*)dyn_smem;        // 8 * 384
    __half2* vs2 = ks2 + 8 * 384;
    int tid = threadIdx.x;
    int wid = tid >> 5, lid = tid & 31;
    int t0 = blockIdx.x * 8;
    for (int i = tid; i < 8 * 384; i += 256) {
        int r = i / 384, c = i - r * 384;
        const __half2* row = (const __half2*)(g_qkv + (size_t)(t0 + r) * NQKV);
        ks2[i] = row[384 + c];
        vs2[i] = row[768 + c];
    }
    __syncthreads();
    int h = wid;
    const __half2* qr = (const __half2*)(g_qkv + (size_t)(t0 + h) * NQKV);
    float2 qv[12];
    #pragma unroll
    for (int j = 0; j < 12; ++j) qv[j] = __half22float2(qr[lid + 32 * j]);
    float p[8];
    #pragma unroll
    for (int kk = 0; kk < 8; ++kk) {
        float acc = 0.f;
        const __half2* kr = ks2 + kk * 384;
        #pragma unroll
        for (int j = 0; j < 12; ++j) {
            float2 k2 = __half22float2(kr[lid + 32 * j]);
            acc += qv[j].x * k2.x + qv[j].y * k2.y;
        }
        p[kk] = acc;
    }
    #pragma unroll
    for (int kk = 0; kk < 8; ++kk) p[kk] = warp_sum(p[kk]) * 0.03608439182435161f;
    float m = p[0];
    #pragma unroll
    for (int kk = 1; kk < 8; ++kk) m = fmaxf(m, p[kk]);
    float se = 0.f;
    #pragma unroll
    for (int kk = 0; kk < 8; ++kk) { p[kk] = __expf(p[kk] - m); se += p[kk]; }
    float rinv = 1.0f / se;
    #pragma unroll
    for (int kk = 0; kk < 8; ++kk) p[kk] *= rinv;
    const float2* xr = (const float2*)(x + (size_t)(t0 + h) * DIMV);
    __half2* yr = (__half2*)(g_y + (size_t)(t0 + h) * DIMV);
    float2 yv[12];
    #pragma unroll
    for (int j = 0; j < 12; ++j) {
        int d = lid + 32 * j;
        float ax = 0.f, ay = 0.f;
        #pragma unroll
        for (int kk = 0; kk < 8; ++kk) {
            float2 v2 = __half22float2(vs2[kk * 384 + d]);
            ax += p[kk] * v2.x;
            ay += p[kk] * v2.y;
        }
        float2 x2 = xr[d];
        yv[j].x = ax + x2.x;
        yv[j].y = ay + x2.y;
        yr[d] = __floats2half2_rn(yv[j].x, yv[j].y);
    }
    float s = 0.f;
    #pragma unroll
    for (int j = 0; j < 12; ++j) s += yv[j].x + yv[j].y;
    float mean = warp_sum(s) * (1.0f / DIMV);
    float s2 = 0.f;
    #pragma unroll
    for (int j = 0; j < 12; ++j) {
        float dx = yv[j].x - mean, dy = yv[j].y - mean;
        s2 += dx * dx + dy * dy;
    }
    float var = warp_sum(s2) * (1.0f / (DIMV - 1));
    float inv = g2[0] / (sqrtf(var) + 1e-6f);
    float bb = b2[0];
    __half2* ar = (__half2*)(g_act + (size_t)(t0 + h) * DIMV);
    #pragma unroll
    for (int j = 0; j < 12; ++j)
        ar[lid + 32 * j] = __floats2half2_rn((yv[j].x - mean) * inv + bb,
                                             (yv[j].y - mean) * inv + bb);
}

// ---------------- fp16 GEMM: 128x128 tile, BK=64, 16 warps (4x4, warp 32x32), 2 CTAs/SM -
// (R11-proven structure: CP_WAIT(1), prefetch distance 2, 3 stages, 64 regs — DO NOT PERTURB)
#define PITCH   144
#define ST_A    18432
#define ST_SIZE 36864
#define N_STAGE 3
#define GEMM_SMEM (N_STAGE * ST_SIZE)

// EPI 0: act @ wqkv^T + qkvb  -> g_qkv (fp16)   (K=768,  N=2304)
// EPI 1: act @ w1^T + d1_b, gelu -> g_h (fp16)  (K=768,  N=3072)
// EPI 2: h @ w2^T + d2_b + g_y -> outF          (K=3072, N=768)
template <int EPI>
__global__ void __launch_bounds__(512, 2) gemm_k(const float* __restrict__ bias, float* __restrict__ outF) {
    constexpr int Kd = (EPI == 2) ? HID : DIMV;
    constexpr int NCH = Kd / 64;
    const __half* A = (EPI == 2) ? g_h : g_act;
    const __half* B = (EPI == 0) ? g_wqkv : (EPI == 1) ? g_w1 : g_w2;

    const int tid = threadIdx.x;
    const int lane = tid & 31, wid = tid >> 5;
    const int wm = wid >> 2, wn = wid & 3;      // 4 x 4 warp grid; warp tile 32 x 32
    const int bx = blockIdx.x, by = blockIdx.y;
    const uint32_t smb = smem_u32(dyn_smem);

    const uint32_t a_off = (uint32_t)(wm * 32 + (lane & 15)) * PITCH + (lane >> 4) * 16;
    const int g = lane >> 3;
    const uint32_t b_off = ST_A + (uint32_t)(wn * 32 + (g >> 1) * 8 + (lane & 7)) * PITCH + (g & 1) * 16;

    auto load_stage = [&](int c, int st) {
        uint32_t sb = smb + st * ST_SIZE;
        #pragma unroll
        for (int j = 0; j < 2; ++j) {
            int id = tid + 512 * j;
            int r = id >> 3, q = id & 7;
            cp16(sb + r * PITCH + q * 16, A + (size_t)(by * 128 + r) * Kd + c * 64 + q * 8);
        }
        #pragma unroll
        for (int j = 0; j < 2; ++j) {
            int id = tid + 512 * j;
            int r = id >> 3, q = id & 7;
            cp16(sb + ST_A + r * PITCH + q * 16, B + (size_t)(bx * 128 + r) * Kd + c * 64 + q * 8);
        }
        CP_COMMIT();
    };

    float acc[2][4][4];
    #pragma unroll
    for (int mi = 0; mi < 2; ++mi)
        #pragma unroll
        for (int ni = 0; ni < 4; ++ni)
            #pragma unroll
            for (int r = 0; r < 4; ++r) acc[mi][ni][r] = 0.f;

    load_stage(0, 0);
    load_stage(1, 1);

    for (int c = 0; c < NCH; ++c) {
        CP_WAIT(1);                              // group c complete
        __syncthreads();                         // stage c visible; buf (c+2)%3 free
        if (c + 2 < NCH) load_stage(c + 2, (c + 2) % N_STAGE);

        const uint32_t sb = smb + (c % N_STAGE) * ST_SIZE;
        #pragma unroll
        for (int ks = 0; ks < 4; ++ks) {
            uint32_t bf[4][2];
            #pragma unroll
            for (int nb = 0; nb < 2; ++nb) {
                uint32_t t[4];
                ldsm_x4(t, sb + b_off + nb * (16 * PITCH) + ks * 32);
                bf[2 * nb][0] = t[0]; bf[2 * nb][1] = t[1];
                bf[2 * nb + 1][0] = t[2]; bf[2 * nb + 1][1] = t[3];
            }
            #pragma unroll
            for (int mi = 0; mi < 2; ++mi) {
                uint32_t a[4];
                ldsm_x4(a, sb + a_off + mi * (16 * PITCH) + ks * 32);
                #pragma unroll
                for (int ni = 0; ni < 4; ++ni)
                    mma16816h(acc[mi][ni], a, bf[ni]);
            }
        }
    }

    // ---------------- epilogue ----------------
    const int r0 = lane >> 2, c0 = 2 * (lane & 3);
    #pragma unroll
    for (int mi = 0; mi < 2; ++mi) {
        #pragma unroll
        for (int hh = 0; hh < 2; ++hh) {
            const int grow = by * 128 + wm * 32 + mi * 16 + r0 + hh * 8;
            #pragma unroll
            for (int ni = 0; ni < 4; ++ni) {
                const int gcol = bx * 128 + wn * 32 + ni * 8 + c0;
                float v0 = acc[mi][ni][2 * hh + 0];
                float v1 = acc[mi][ni][2 * hh + 1];
                if (EPI == 0) {
                    size_t idx = (size_t)grow * NQKV + gcol;
                    *(__half2*)(g_qkv + idx) =
                        __half2(__float2half(v0 + g_qkvb[gcol]), __float2half(v1 + g_qkvb[gcol + 1]));
                } else if (EPI == 1) {
                    float u0 = v0 + bias[gcol];
                    float u1 = v1 + bias[gcol + 1];
                    float gl0 = 0.5f * u0 * (1.0f + erff(u0 * 0.70710678118654752440f));
                    float gl1 = 0.5f * u1 * (1.0f + erff(u1 * 0.70710678118654752440f));
                    size_t idx = (size_t)grow * HID + gcol;
                    *(__half2*)(g_h + idx) = __half2(__float2half(gl0), __float2half(gl1));
                } else {
                    size_t idx = (size_t)grow * DIMV + gcol;
                    float2 res = __half22float2(*(const __half2*)(g_y + idx));
                    float2 o;
                    o.x = v0 + bias[gcol] + res.x;
                    o.y = v1 + bias[gcol + 1] + res.y;
                    *(float2*)(outF + idx) = o;
                }
            }
        }
    }
}

// ---------------- launch ----------------
#define ATTN_SMEM (2 * 8 * 384 * (int)sizeof(__half2))

extern "C" void kernel_launch(void* const* d_in, const int* in_sizes, int n_in,
                              void* d_out, int out_size) {
    const float* x    = (const float*)d_in[0];
    const float* wq_w = (const float*)d_in[1];
    const float* wq_b = (const float*)d_in[2];
    const float* wk_w = (const float*)d_in[3];
    const float* wk_b = (const float*)d_in[4];
    const float* wv_w = (const float*)d_in[5];
    const float* wv_b = (const float*)d_in[6];
    const float* d1_w = (const float*)d_in[7];
    const float* d1_b = (const float*)d_in[8];
    const float* d2_w = (const float*)d_in[9];
    const float* d2_b = (const float*)d_in[10];
    const float* g1   = (const float*)d_in[11];
    const float* b1   = (const float*)d_in[12];
    const float* g2   = (const float*)d_in[13];
    const float* b2   = (const float*)d_in[14];
    float* out = (float*)d_out;

    cudaFuncSetAttribute(gemm_k<0>, cudaFuncAttributeMaxDynamicSharedMemorySize, GEMM_SMEM);
    cudaFuncSetAttribute(gemm_k<1>, cudaFuncAttributeMaxDynamicSharedMemorySize, GEMM_SMEM);
    cudaFuncSetAttribute(gemm_k<2>, cudaFuncAttributeMaxDynamicSharedMemorySize, GEMM_SMEM);
    cudaFuncSetAttribute(attn_ln2_kernel, cudaFuncAttributeMaxDynamicSharedMemorySize, ATTN_SMEM);

    prep_all<<<4096, 256>>>(wq_w, wk_w, wv_w, wq_b, wk_b, wv_b, d1_w, d2_w);        // 0
    ln1_kernel<<<TTOK / 8, 256>>>(x, g1, b1);                                       // 1
    gemm_k<0><<<dim3(NQKV / 128, TTOK / 128), 512, GEMM_SMEM>>>(nullptr, nullptr);  // 2
    attn_ln2_kernel<<<TTOK / 8, 256, ATTN_SMEM>>>(x, g2, b2);                       // 3
    gemm_k<1><<<dim3(HID / 128, TTOK / 128), 512, GEMM_SMEM>>>(d1_b, nullptr);      // 4
    gemm_k<2><<<dim3(DIMV / 128, TTOK / 128), 512, GEMM_SMEM>>>(d2_b, out);         // 5 <- profiled
}

// round 16
// speedup vs baseline: 1.2085x; 1.0029x over previous
#include <cuda_runtime.h>
#include <cuda_bf16.h>
#include <cuda_fp16.h>
#include <cstdint>

#define DIMV 768
#define TTOK 16384
#define HID  3072
#define NQKV 2304

// ---------------- device scratch (allocation-free rule: __device__ globals) -------------
__device__ __align__(256) __half g_act[(size_t)TTOK * DIMV];
__device__ __align__(256) __half g_qkv[(size_t)TTOK * NQKV];
__device__ __align__(256) __half g_y[(size_t)TTOK * DIMV];
__device__ __align__(256) __half g_h[(size_t)TTOK * HID];
__device__ __align__(256) __half g_wqkv[(size_t)NQKV * DIMV];
__device__ __align__(256) __half g_w1[(size_t)HID * DIMV];
__device__ __align__(256) __half g_w2[(size_t)DIMV * HID];
__device__ __align__(256) float  g_qkvb[NQKV];

extern __shared__ char dyn_smem[];

// ---------------- PTX helpers ----------------
__device__ __forceinline__ uint32_t smem_u32(const void* p) {
    uint32_t a;
    asm("{ .reg .u64 t; cvta.to.shared.u64 t, %1; cvt.u32.u64 %0, t; }" : "=r"(a) : "l"(p));
    return a;
}
__device__ __forceinline__ void cp16(uint32_t smaddr, const void* g) {
    asm volatile("cp.async.cg.shared.global [%0], [%1], 16;" :: "r"(smaddr), "l"(g) : "memory");
}
#define CP_COMMIT() asm volatile("cp.async.commit_group;" ::: "memory")
#define CP_WAIT(n)  asm volatile("cp.async.wait_group %0;" :: "n"(n) : "memory")

__device__ __forceinline__ void ldsm_x4(uint32_t* r, uint32_t addr) {
    asm volatile("ldmatrix.sync.aligned.m8n8.x4.shared.b16 {%0,%1,%2,%3}, [%4];"
                 : "=r"(r[0]), "=r"(r[1]), "=r"(r[2]), "=r"(r[3]) : "r"(addr));
}
__device__ __forceinline__ void mma16816h(float* c, const uint32_t* a, const uint32_t* b) {
    asm volatile("mma.sync.aligned.m16n8k16.row.col.f32.f16.f16.f32 "
                 "{%0,%1,%2,%3}, {%4,%5,%6,%7}, {%8,%9}, {%0,%1,%2,%3};"
                 : "+f"(c[0]), "+f"(c[1]), "+f"(c[2]), "+f"(c[3])
                 : "r"(a[0]), "r"(a[1]), "r"(a[2]), "r"(a[3]), "r"(b[0]), "r"(b[1]));
}

// ---------------- small helpers ----------------
__device__ __forceinline__ float warp_sum(float v) {
    #pragma unroll
    for (int o = 16; o > 0; o >>= 1) v += __shfl_xor_sync(0xffffffffu, v, o);
    return v;
}

// ---------------- merged prep + LN1 in one launch ----------------
// blocks [0, 4096): weight fp16 conversion + bias concat (grid-stride)
// blocks [4096, 6144): LN1 (warp-per-token, 8 tokens/block)
#define PREP_BLOCKS 4096
#define LN1_BLOCKS  (TTOK / 8)
__global__ void prep_ln1_kernel(const float* __restrict__ wq, const float* __restrict__ wk,
                                const float* __restrict__ wv, const float* __restrict__ bq,
                                const float* __restrict__ bk, const float* __restrict__ bv,
                                const float* __restrict__ d1, const float* __restrict__ d2,
                                const float* __restrict__ x, const float* __restrict__ g1,
                                const float* __restrict__ b1) {
    if (blockIdx.x < PREP_BLOCKS) {
        const int n = DIMV * DIMV;
        const int m = HID * DIMV;
        const int t0 = 3 * n;
        const int t1 = t0 + NQKV;
        const int t2 = t1 + m;
        const int total = t2 + m;
        for (int i = blockIdx.x * blockDim.x + threadIdx.x; i < total; i += PREP_BLOCKS * blockDim.x) {
            if (i < t0) {
                int s = i / n, j = i - s * n;
                const float* w = (s == 0) ? wq : (s == 1) ? wk : wv;
                g_wqkv[(size_t)s * n + j] = __float2half(w[j]);
            } else if (i < t1) {
                int j = i - t0;
                g_qkvb[j] = (j < 768) ? bq[j] : (j < 1536) ? bk[j - 768] : bv[j - 1536];
            } else if (i < t2) {
                int j = i - t1;
                g_w1[j] = __float2half(d1[j]);
            } else {
                int j = i - t2;
                g_w2[j] = __float2half(d2[j]);
            }
        }
    } else {
        int wid = threadIdx.x >> 5, lid = threadIdx.x & 31;
        int tok = (blockIdx.x - PREP_BLOCKS) * 8 + wid;
        const float2* xr = (const float2*)(x + (size_t)tok * DIMV);
        float2 xv[12];
        #pragma unroll
        for (int j = 0; j < 12; ++j) xv[j] = xr[lid + 32 * j];
        float s = 0.f;
        #pragma unroll
        for (int j = 0; j < 12; ++j) s += xv[j].x + xv[j].y;
        float mean = warp_sum(s) * (1.0f / DIMV);
        float s2 = 0.f;
        #pragma unroll
        for (int j = 0; j < 12; ++j) {
            float dx = xv[j].x - mean, dy = xv[j].y - mean;
            s2 += dx * dx + dy * dy;
        }
        float var = warp_sum(s2) * (1.0f / (DIMV - 1));
        float inv = g1[0] / (sqrtf(var) + 1e-6f);
        float bb = b1[0];
        __half2* ar = (__half2*)(g_act + (size_t)tok * DIMV);
        #pragma unroll
        for (int j = 0; j < 12; ++j)
            ar[lid + 32 * j] = __floats2half2_rn((xv[j].x - mean) * inv + bb,
                                                 (xv[j].y - mean) * inv + bb);
    }
}

// ---------------- attention + residual + LN2 (k/v fp16 smem; y fp16) ----------------
__global__ void __launch_bounds__(256, 6) attn_ln2_kernel(
        const float* __restrict__ x, const float* __restrict__ g2, const float* __restrict__ b2) {
    __half2* ks2 = (__half2*)dyn_smem;        // 8 * 384
    __half2* vs2 = ks2 + 8 * 384;
    int tid = threadIdx.x;
    int wid = tid >> 5, lid = tid & 31;
    int t0 = blockIdx.x * 8;
    for (int i = tid; i < 8 * 384; i += 256) {
        int r = i / 384, c = i - r * 384;
        const __half2* row = (const __half2*)(g_qkv + (size_t)(t0 + r) * NQKV);
        ks2[i] = row[384 + c];
        vs2[i] = row[768 + c];
    }
    __syncthreads();
    int h = wid;
    const __half2* qr = (const __half2*)(g_qkv + (size_t)(t0 + h) * NQKV);
    float2 qv[12];
    #pragma unroll
    for (int j = 0; j < 12; ++j) qv[j] = __half22float2(qr[lid + 32 * j]);
    float p[8];
    #pragma unroll
    for (int kk = 0; kk < 8; ++kk) {
        float acc = 0.f;
        const __half2* kr = ks2 + kk * 384;
        #pragma unroll
        for (int j = 0; j < 12; ++j) {
            float2 k2 = __half22float2(kr[lid + 32 * j]);
            acc += qv[j].x * k2.x + qv[j].y * k2.y;
        }
        p[kk] = acc;
    }
    #pragma unroll
    for (int kk = 0; kk < 8; ++kk) p[kk] = warp_sum(p[kk]) * 0.03608439182435161f;
    float m = p[0];
    #pragma unroll
    for (int kk = 1; kk < 8; ++kk) m = fmaxf(m, p[kk]);
    float se = 0.f;
    #pragma unroll
    for (int kk = 0; kk < 8; ++kk) { p[kk] = __expf(p[kk] - m); se += p[kk]; }
    float rinv = 1.0f / se;
    #pragma unroll
    for (int kk = 0; kk < 8; ++kk) p[kk] *= rinv;
    const float2* xr = (const float2*)(x + (size_t)(t0 + h) * DIMV);
    __half2* yr = (__half2*)(g_y + (size_t)(t0 + h) * DIMV);
    float2 yv[12];
    #pragma unroll
    for (int j = 0; j < 12; ++j) {
        int d = lid + 32 * j;
        float ax = 0.f, ay = 0.f;
        #pragma unroll
        for (int kk = 0; kk < 8; ++kk) {
            float2 v2 = __half22float2(vs2[kk * 384 + d]);
            ax += p[kk] * v2.x;
            ay += p[kk] * v2.y;
        }
        float2 x2 = xr[d];
        yv[j].x = ax + x2.x;
        yv[j].y = ay + x2.y;
        yr[d] = __floats2half2_rn(yv[j].x, yv[j].y);
    }
    float s = 0.f;
    #pragma unroll
    for (int j = 0; j < 12; ++j) s += yv[j].x + yv[j].y;
    float mean = warp_sum(s) * (1.0f / DIMV);
    float s2 = 0.f;
    #pragma unroll
    for (int j = 0; j < 12; ++j) {
        float dx = yv[j].x - mean, dy = yv[j].y - mean;
        s2 += dx * dx + dy * dy;
    }
    float var = warp_sum(s2) * (1.0f / (DIMV - 1));
    float inv = g2[0] / (sqrtf(var) + 1e-6f);
    float bb = b2[0];
    __half2* ar = (__half2*)(g_act + (size_t)(t0 + h) * DIMV);
    #pragma unroll
    for (int j = 0; j < 12; ++j)
        ar[lid + 32 * j] = __floats2half2_rn((yv[j].x - mean) * inv + bb,
                                             (yv[j].y - mean) * inv + bb);
}

// ---------------- fp16 GEMM: 128x128 tile, BK=64, 16 warps (4x4, warp 32x32), 2 CTAs/SM -
// (R11-proven structure: CP_WAIT(1), prefetch distance 2, 3 stages, 64 regs — DO NOT PERTURB)
#define PITCH   144
#define ST_A    18432
#define ST_SIZE 36864
#define N_STAGE 3
#define GEMM_SMEM (N_STAGE * ST_SIZE)

// EPI 0: act @ wqkv^T + qkvb  -> g_qkv (fp16)   (K=768,  N=2304)
// EPI 1: act @ w1^T + d1_b, gelu -> g_h (fp16)  (K=768,  N=3072)
// EPI 2: h @ w2^T + d2_b + g_y -> outF          (K=3072, N=768)
template <int EPI>
__global__ void __launch_bounds__(512, 2) gemm_k(const float* __restrict__ bias, float* __restrict__ outF) {
    constexpr int Kd = (EPI == 2) ? HID : DIMV;
    constexpr int NCH = Kd / 64;
    const __half* A = (EPI == 2) ? g_h : g_act;
    const __half* B = (EPI == 0) ? g_wqkv : (EPI == 1) ? g_w1 : g_w2;

    const int tid = threadIdx.x;
    const int lane = tid & 31, wid = tid >> 5;
    const int wm = wid >> 2, wn = wid & 3;      // 4 x 4 warp grid; warp tile 32 x 32
    const int bx = blockIdx.x, by = blockIdx.y;
    const uint32_t smb = smem_u32(dyn_smem);

    const uint32_t a_off = (uint32_t)(wm * 32 + (lane & 15)) * PITCH + (lane >> 4) * 16;
    const int g = lane >> 3;
    const uint32_t b_off = ST_A + (uint32_t)(wn * 32 + (g >> 1) * 8 + (lane & 7)) * PITCH + (g & 1) * 16;

    auto load_stage = [&](int c, int st) {
        uint32_t sb = smb + st * ST_SIZE;
        #pragma unroll
        for (int j = 0; j < 2; ++j) {
            int id = tid + 512 * j;
            int r = id >> 3, q = id & 7;
            cp16(sb + r * PITCH + q * 16, A + (size_t)(by * 128 + r) * Kd + c * 64 + q * 8);
        }
        #pragma unroll
        for (int j = 0; j < 2; ++j) {
            int id = tid + 512 * j;
            int r = id >> 3, q = id & 7;
            cp16(sb + ST_A + r * PITCH + q * 16, B + (size_t)(bx * 128 + r) * Kd + c * 64 + q * 8);
        }
        CP_COMMIT();
    };

    float acc[2][4][4];
    #pragma unroll
    for (int mi = 0; mi < 2; ++mi)
        #pragma unroll
        for (int ni = 0; ni < 4; ++ni)
            #pragma unroll
            for (int r = 0; r < 4; ++r) acc[mi][ni][r] = 0.f;

    load_stage(0, 0);
    load_stage(1, 1);

    for (int c = 0; c < NCH; ++c) {
        CP_WAIT(1);                              // group c complete
        __syncthreads();                         // stage c visible; buf (c+2)%3 free
        if (c + 2 < NCH) load_stage(c + 2, (c + 2) % N_STAGE);

        const uint32_t sb = smb + (c % N_STAGE) * ST_SIZE;
        #pragma unroll
        for (int ks = 0; ks < 4; ++ks) {
            uint32_t bf[4][2];
            #pragma unroll
            for (int nb = 0; nb < 2; ++nb) {
                uint32_t t[4];
                ldsm_x4(t, sb + b_off + nb * (16 * PITCH) + ks * 32);
                bf[2 * nb][0] = t[0]; bf[2 * nb][1] = t[1];
                bf[2 * nb + 1][0] = t[2]; bf[2 * nb + 1][1] = t[3];
            }
            #pragma unroll
            for (int mi = 0; mi < 2; ++mi) {
                uint32_t a[4];
                ldsm_x4(a, sb + a_off + mi * (16 * PITCH) + ks * 32);
                #pragma unroll
                for (int ni = 0; ni < 4; ++ni)
                    mma16816h(acc[mi][ni], a, bf[ni]);
            }
        }
    }

    // ---------------- epilogue ----------------
    const int r0 = lane >> 2, c0 = 2 * (lane & 3);
    #pragma unroll
    for (int mi = 0; mi < 2; ++mi) {
        #pragma unroll
        for (int hh = 0; hh < 2; ++hh) {
            const int grow = by * 128 + wm * 32 + mi * 16 + r0 + hh * 8;
            #pragma unroll
            for (int ni = 0; ni < 4; ++ni) {
                const int gcol = bx * 128 + wn * 32 + ni * 8 + c0;
                float v0 = acc[mi][ni][2 * hh + 0];
                float v1 = acc[mi][ni][2 * hh + 1];
                if (EPI == 0) {
                    size_t idx = (size_t)grow * NQKV + gcol;
                    *(__half2*)(g_qkv + idx) =
                        __half2(__float2half(v0 + g_qkvb[gcol]), __float2half(v1 + g_qkvb[gcol + 1]));
                } else if (EPI == 1) {
                    float u0 = v0 + bias[gcol];
                    float u1 = v1 + bias[gcol + 1];
                    float gl0 = 0.5f * u0 * (1.0f + erff(u0 * 0.70710678118654752440f));
                    float gl1 = 0.5f * u1 * (1.0f + erff(u1 * 0.70710678118654752440f));
                    size_t idx = (size_t)grow * HID + gcol;
                    *(__half2*)(g_h + idx) = __half2(__float2half(gl0), __float2half(gl1));
                } else {
                    size_t idx = (size_t)grow * DIMV + gcol;
                    float2 res = __half22float2(*(const __half2*)(g_y + idx));
                    float2 o;
                    o.x = v0 + bias[gcol] + res.x;
                    o.y = v1 + bias[gcol + 1] + res.y;
                    *(float2*)(outF + idx) = o;
                }
            }
        }
    }
}

// ---------------- launch ----------------
#define ATTN_SMEM (2 * 8 * 384 * (int)sizeof(__half2))

extern "C" void kernel_launch(void* const* d_in, const int* in_sizes, int n_in,
                              void* d_out, int out_size) {
    const float* x    = (const float*)d_in[0];
    const float* wq_w = (const float*)d_in[1];
    const float* wq_b = (const float*)d_in[2];
    const float* wk_w = (const float*)d_in[3];
    const float* wk_b = (const float*)d_in[4];
    const float* wv_w = (const float*)d_in[5];
    const float* wv_b = (const float*)d_in[6];
    const float* d1_w = (const float*)d_in[7];
    const float* d1_b = (const float*)d_in[8];
    const float* d2_w = (const float*)d_in[9];
    const float* d2_b = (const float*)d_in[10];
    const float* g1   = (const float*)d_in[11];
    const float* b1   = (const float*)d_in[12];
    const float* g2   = (const float*)d_in[13];
    const float* b2   = (const float*)d_in[14];
    float* out = (float*)d_out;

    cudaFuncSetAttribute(gemm_k<0>, cudaFuncAttributeMaxDynamicSharedMemorySize, GEMM_SMEM);
    cudaFuncSetAttribute(gemm_k<1>, cudaFuncAttributeMaxDynamicSharedMemorySize, GEMM_SMEM);
    cudaFuncSetAttribute(gemm_k<2>, cudaFuncAttributeMaxDynamicSharedMemorySize, GEMM_SMEM);
    cudaFuncSetAttribute(attn_ln2_kernel, cudaFuncAttributeMaxDynamicSharedMemorySize, ATTN_SMEM);

    prep_ln1_kernel<<<PREP_BLOCKS + LN1_BLOCKS, 256>>>(
        wq_w, wk_w, wv_w, wq_b, wk_b, wv_b, d1_w, d2_w, x, g1, b1);                 // 0
    gemm_k<0><<<dim3(NQKV / 128, TTOK / 128), 512, GEMM_SMEM>>>(nullptr, nullptr);  // 1
    attn_ln2_kernel<<<TTOK / 8, 256, ATTN_SMEM>>>(x, g2, b2);                       // 2
    gemm_k<1><<<dim3(HID / 128, TTOK / 128), 512, GEMM_SMEM>>>(d1_b, nullptr);      // 3
    gemm_k<2><<<dim3(DIMV / 128, TTOK / 128), 512, GEMM_SMEM>>>(d2_b, out);         // 4
}

// round 17
// speedup vs baseline: 1.2515x; 1.0356x over previous
#include <cuda_runtime.h>
#include <cuda_bf16.h>
#include <cuda_fp16.h>
#include <cstdint>

#define DIMV 768
#define TTOK 16384
#define HID  3072
#define NQKV 2304

// ---------------- device scratch (allocation-free rule: __device__ globals) -------------
__device__ __align__(256) __half g_act[(size_t)TTOK * DIMV];
__device__ __align__(256) __half g_qkv[(size_t)TTOK * NQKV];
__device__ __align__(256) __half g_y[(size_t)TTOK * DIMV];
__device__ __align__(256) __half g_h[(size_t)TTOK * HID];
__device__ __align__(256) __half g_wqkv[(size_t)NQKV * DIMV];
__device__ __align__(256) __half g_w1[(size_t)HID * DIMV];
__device__ __align__(256) __half g_w2[(size_t)DIMV * HID];
__device__ __align__(256) float  g_qkvb[NQKV];

extern __shared__ char dyn_smem[];

// ---------------- PTX helpers ----------------
__device__ __forceinline__ uint32_t smem_u32(const void* p) {
    uint32_t a;
    asm("{ .reg .u64 t; cvta.to.shared.u64 t, %1; cvt.u32.u64 %0, t; }" : "=r"(a) : "l"(p));
    return a;
}
__device__ __forceinline__ void cp16(uint32_t smaddr, const void* g) {
    asm volatile("cp.async.cg.shared.global [%0], [%1], 16;" :: "r"(smaddr), "l"(g) : "memory");
}
#define CP_COMMIT() asm volatile("cp.async.commit_group;" ::: "memory")
#define CP_WAIT(n)  asm volatile("cp.async.wait_group %0;" :: "n"(n) : "memory")

__device__ __forceinline__ void ldsm_x4(uint32_t* r, uint32_t addr) {
    asm volatile("ldmatrix.sync.aligned.m8n8.x4.shared.b16 {%0,%1,%2,%3}, [%4];"
                 : "=r"(r[0]), "=r"(r[1]), "=r"(r[2]), "=r"(r[3]) : "r"(addr));
}
__device__ __forceinline__ void mma16816h(float* c, const uint32_t* a, const uint32_t* b) {
    asm volatile("mma.sync.aligned.m16n8k16.row.col.f32.f16.f16.f32 "
                 "{%0,%1,%2,%3}, {%4,%5,%6,%7}, {%8,%9}, {%0,%1,%2,%3};"
                 : "+f"(c[0]), "+f"(c[1]), "+f"(c[2]), "+f"(c[3])
                 : "r"(a[0]), "r"(a[1]), "r"(a[2]), "r"(a[3]), "r"(b[0]), "r"(b[1]));
}
// hardware tanh (sm_75+; max err ~2^-11) for the GELU epilogue
__device__ __forceinline__ float fast_tanh(float x) {
    float y;
    asm("tanh.approx.f32 %0, %1;" : "=f"(y) : "f"(x));
    return y;
}
__device__ __forceinline__ float gelu_fast(float u) {
    float w = 0.79788456080286536f * u * (1.0f + 0.044715f * u * u);
    return 0.5f * u * (1.0f + fast_tanh(w));
}

// ---------------- small helpers ----------------
__device__ __forceinline__ float warp_sum(float v) {
    #pragma unroll
    for (int o = 16; o > 0; o >>= 1) v += __shfl_xor_sync(0xffffffffu, v, o);
    return v;
}

// ---------------- merged prep + LN1 in one launch ----------------
#define PREP_BLOCKS 4096
#define LN1_BLOCKS  (TTOK / 8)
__global__ void prep_ln1_kernel(const float* __restrict__ wq, const float* __restrict__ wk,
                                const float* __restrict__ wv, const float* __restrict__ bq,
                                const float* __restrict__ bk, const float* __restrict__ bv,
                                const float* __restrict__ d1, const float* __restrict__ d2,
                                const float* __restrict__ x, const float* __restrict__ g1,
                                const float* __restrict__ b1) {
    if (blockIdx.x < PREP_BLOCKS) {
        const int n = DIMV * DIMV;
        const int m = HID * DIMV;
        const int t0 = 3 * n;
        const int t1 = t0 + NQKV;
        const int t2 = t1 + m;
        const int total = t2 + m;
        for (int i = blockIdx.x * blockDim.x + threadIdx.x; i < total; i += PREP_BLOCKS * blockDim.x) {
            if (i < t0) {
                int s = i / n, j = i - s * n;
                const float* w = (s == 0) ? wq : (s == 1) ? wk : wv;
                g_wqkv[(size_t)s * n + j] = __float2half(w[j]);
            } else if (i < t1) {
                int j = i - t0;
                g_qkvb[j] = (j < 768) ? bq[j] : (j < 1536) ? bk[j - 768] : bv[j - 1536];
            } else if (i < t2) {
                int j = i - t1;
                g_w1[j] = __float2half(d1[j]);
            } else {
                int j = i - t2;
                g_w2[j] = __float2half(d2[j]);
            }
        }
    } else {
        int wid = threadIdx.x >> 5, lid = threadIdx.x & 31;
        int tok = (blockIdx.x - PREP_BLOCKS) * 8 + wid;
        const float2* xr = (const float2*)(x + (size_t)tok * DIMV);
        float2 xv[12];
        #pragma unroll
        for (int j = 0; j < 12; ++j) xv[j] = xr[lid + 32 * j];
        float s = 0.f;
        #pragma unroll
        for (int j = 0; j < 12; ++j) s += xv[j].x + xv[j].y;
        float mean = warp_sum(s) * (1.0f / DIMV);
        float s2 = 0.f;
        #pragma unroll
        for (int j = 0; j < 12; ++j) {
            float dx = xv[j].x - mean, dy = xv[j].y - mean;
            s2 += dx * dx + dy * dy;
        }
        float var = warp_sum(s2) * (1.0f / (DIMV - 1));
        float inv = g1[0] / (sqrtf(var) + 1e-6f);
        float bb = b1[0];
        __half2* ar = (__half2*)(g_act + (size_t)tok * DIMV);
        #pragma unroll
        for (int j = 0; j < 12; ++j)
            ar[lid + 32 * j] = __floats2half2_rn((xv[j].x - mean) * inv + bb,
                                                 (xv[j].y - mean) * inv + bb);
    }
}

// ---------------- attention + residual + LN2 (k/v fp16 smem; y fp16) ----------------
__global__ void __launch_bounds__(256, 6) attn_ln2_kernel(
        const float* __restrict__ x, const float* __restrict__ g2, const float* __restrict__ b2) {
    __half2* ks2 = (__half2*)dyn_smem;        // 8 * 384
    __half2* vs2 = ks2 + 8 * 384;
    int tid = threadIdx.x;
    int wid = tid >> 5, lid = tid & 31;
    int t0 = blockIdx.x * 8;
    for (int i = tid; i < 8 * 384; i += 256) {
        int r = i / 384, c = i - r * 384;
        const __half2* row = (const __half2*)(g_qkv + (size_t)(t0 + r) * NQKV);
        ks2[i] = row[384 + c];
        vs2[i] = row[768 + c];
    }
    __syncthreads();
    int h = wid;
    const __half2* qr = (const __half2*)(g_qkv + (size_t)(t0 + h) * NQKV);
    float2 qv[12];
    #pragma unroll
    for (int j = 0; j < 12; ++j) qv[j] = __half22float2(qr[lid + 32 * j]);
    float p[8];
    #pragma unroll
    for (int kk = 0; kk < 8; ++kk) {
        float acc = 0.f;
        const __half2* kr = ks2 + kk * 384;
        #pragma unroll
        for (int j = 0; j < 12; ++j) {
            float2 k2 = __half22float2(kr[lid + 32 * j]);
            acc += qv[j].x * k2.x + qv[j].y * k2.y;
        }
        p[kk] = acc;
    }
    #pragma unroll
    for (int kk = 0; kk < 8; ++kk) p[kk] = warp_sum(p[kk]) * 0.03608439182435161f;
    float m = p[0];
    #pragma unroll
    for (int kk = 1; kk < 8; ++kk) m = fmaxf(m, p[kk]);
    float se = 0.f;
    #pragma unroll
    for (int kk = 0; kk < 8; ++kk) { p[kk] = __expf(p[kk] - m); se += p[kk]; }
    float rinv = 1.0f / se;
    #pragma unroll
    for (int kk = 0; kk < 8; ++kk) p[kk] *= rinv;
    const float2* xr = (const float2*)(x + (size_t)(t0 + h) * DIMV);
    __half2* yr = (__half2*)(g_y + (size_t)(t0 + h) * DIMV);
    float2 yv[12];
    #pragma unroll
    for (int j = 0; j < 12; ++j) {
        int d = lid + 32 * j;
        float ax = 0.f, ay = 0.f;
        #pragma unroll
        for (int kk = 0; kk < 8; ++kk) {
            float2 v2 = __half22float2(vs2[kk * 384 + d]);
            ax += p[kk] * v2.x;
            ay += p[kk] * v2.y;
        }
        float2 x2 = xr[d];
        yv[j].x = ax + x2.x;
        yv[j].y = ay + x2.y;
        yr[d] = __floats2half2_rn(yv[j].x, yv[j].y);
    }
    float s = 0.f;
    #pragma unroll
    for (int j = 0; j < 12; ++j) s += yv[j].x + yv[j].y;
    float mean = warp_sum(s) * (1.0f / DIMV);
    float s2 = 0.f;
    #pragma unroll
    for (int j = 0; j < 12; ++j) {
        float dx = yv[j].x - mean, dy = yv[j].y - mean;
        s2 += dx * dx + dy * dy;
    }
    float var = warp_sum(s2) * (1.0f / (DIMV - 1));
    float inv = g2[0] / (sqrtf(var) + 1e-6f);
    float bb = b2[0];
    __half2* ar = (__half2*)(g_act + (size_t)(t0 + h) * DIMV);
    #pragma unroll
    for (int j = 0; j < 12; ++j)
        ar[lid + 32 * j] = __floats2half2_rn((yv[j].x - mean) * inv + bb,
                                             (yv[j].y - mean) * inv + bb);
}

// ---------------- fp16 GEMM: 128x128 tile, BK=64, 16 warps (4x4, warp 32x32), 2 CTAs/SM -
// (R11-proven structure: CP_WAIT(1), prefetch distance 2, 3 stages, 64 regs — DO NOT PERTURB)
#define PITCH   144
#define ST_A    18432
#define ST_SIZE 36864
#define N_STAGE 3
#define GEMM_SMEM (N_STAGE * ST_SIZE)

// EPI 0: act @ wqkv^T + qkvb  -> g_qkv (fp16)   (K=768,  N=2304)
// EPI 1: act @ w1^T + d1_b, gelu -> g_h (fp16)  (K=768,  N=3072)
// EPI 2: h @ w2^T + d2_b + g_y -> outF          (K=3072, N=768)
template <int EPI>
__global__ void __launch_bounds__(512, 2) gemm_k(const float* __restrict__ bias, float* __restrict__ outF) {
    constexpr int Kd = (EPI == 2) ? HID : DIMV;
    constexpr int NCH = Kd / 64;
    const __half* A = (EPI == 2) ? g_h : g_act;
    const __half* B = (EPI == 0) ? g_wqkv : (EPI == 1) ? g_w1 : g_w2;

    const int tid = threadIdx.x;
    const int lane = tid & 31, wid = tid >> 5;
    const int wm = wid >> 2, wn = wid & 3;      // 4 x 4 warp grid; warp tile 32 x 32
    const int bx = blockIdx.x, by = blockIdx.y;
    const uint32_t smb = smem_u32(dyn_smem);

    const uint32_t a_off = (uint32_t)(wm * 32 + (lane & 15)) * PITCH + (lane >> 4) * 16;
    const int g = lane >> 3;
    const uint32_t b_off = ST_A + (uint32_t)(wn * 32 + (g >> 1) * 8 + (lane & 7)) * PITCH + (g & 1) * 16;

    auto load_stage = [&](int c, int st) {
        uint32_t sb = smb + st * ST_SIZE;
        #pragma unroll
        for (int j = 0; j < 2; ++j) {
            int id = tid + 512 * j;
            int r = id >> 3, q = id & 7;
            cp16(sb + r * PITCH + q * 16, A + (size_t)(by * 128 + r) * Kd + c * 64 + q * 8);
        }
        #pragma unroll
        for (int j = 0; j < 2; ++j) {
            int id = tid + 512 * j;
            int r = id >> 3, q = id & 7;
            cp16(sb + ST_A + r * PITCH + q * 16, B + (size_t)(bx * 128 + r) * Kd + c * 64 + q * 8);
        }
        CP_COMMIT();
    };

    float acc[2][4][4];
    #pragma unroll
    for (int mi = 0; mi < 2; ++mi)
        #pragma unroll
        for (int ni = 0; ni < 4; ++ni)
            #pragma unroll
            for (int r = 0; r < 4; ++r) acc[mi][ni][r] = 0.f;

    load_stage(0, 0);
    load_stage(1, 1);

    for (int c = 0; c < NCH; ++c) {
        CP_WAIT(1);                              // group c complete
        __syncthreads();                         // stage c visible; buf (c+2)%3 free
        if (c + 2 < NCH) load_stage(c + 2, (c + 2) % N_STAGE);

        const uint32_t sb = smb + (c % N_STAGE) * ST_SIZE;
        #pragma unroll
        for (int ks = 0; ks < 4; ++ks) {
            uint32_t bf[4][2];
            #pragma unroll
            for (int nb = 0; nb < 2; ++nb) {
                uint32_t t[4];
                ldsm_x4(t, sb + b_off + nb * (16 * PITCH) + ks * 32);
                bf[2 * nb][0] = t[0]; bf[2 * nb][1] = t[1];
                bf[2 * nb + 1][0] = t[2]; bf[2 * nb + 1][1] = t[3];
            }
            #pragma unroll
            for (int mi = 0; mi < 2; ++mi) {
                uint32_t a[4];
                ldsm_x4(a, sb + a_off + mi * (16 * PITCH) + ks * 32);
                #pragma unroll
                for (int ni = 0; ni < 4; ++ni)
                    mma16816h(acc[mi][ni], a, bf[ni]);
            }
        }
    }

    // ---------------- epilogue ----------------
    const int r0 = lane >> 2, c0 = 2 * (lane & 3);
    #pragma unroll
    for (int mi = 0; mi < 2; ++mi) {
        #pragma unroll
        for (int hh = 0; hh < 2; ++hh) {
            const int grow = by * 128 + wm * 32 + mi * 16 + r0 + hh * 8;
            #pragma unroll
            for (int ni = 0; ni < 4; ++ni) {
                const int gcol = bx * 128 + wn * 32 + ni * 8 + c0;
                float v0 = acc[mi][ni][2 * hh + 0];
                float v1 = acc[mi][ni][2 * hh + 1];
                if (EPI == 0) {
                    size_t idx = (size_t)grow * NQKV + gcol;
                    *(__half2*)(g_qkv + idx) =
                        __half2(__float2half(v0 + g_qkvb[gcol]), __float2half(v1 + g_qkvb[gcol + 1]));
                } else if (EPI == 1) {
                    float u0 = v0 + bias[gcol];
                    float u1 = v1 + bias[gcol + 1];
                    float gl0 = gelu_fast(u0);
                    float gl1 = gelu_fast(u1);
                    size_t idx = (size_t)grow * HID + gcol;
                    *(__half2*)(g_h + idx) = __half2(__float2half(gl0), __float2half(gl1));
                } else {
                    size_t idx = (size_t)grow * DIMV + gcol;
                    float2 res = __half22float2(*(const __half2*)(g_y + idx));
                    float2 o;
                    o.x = v0 + bias[gcol] + res.x;
                    o.y = v1 + bias[gcol + 1] + res.y;
                    *(float2*)(outF + idx) = o;
                }
            }
        }
    }
}

// ---------------- launch ----------------
#define ATTN_SMEM (2 * 8 * 384 * (int)sizeof(__half2))

extern "C" void kernel_launch(void* const* d_in, const int* in_sizes, int n_in,
                              void* d_out, int out_size) {
    const float* x    = (const float*)d_in[0];
    const float* wq_w = (const float*)d_in[1];
    const float* wq_b = (const float*)d_in[2];
    const float* wk_w = (const float*)d_in[3];
    const float* wk_b = (const float*)d_in[4];
    const float* wv_w = (const float*)d_in[5];
    const float* wv_b = (const float*)d_in[6];
    const float* d1_w = (const float*)d_in[7];
    const float* d1_b = (const float*)d_in[8];
    const float* d2_w = (const float*)d_in[9];
    const float* d2_b = (const float*)d_in[10];
    const float* g1   = (const float*)d_in[11];
    const float* b1   = (const float*)d_in[12];
    const float* g2   = (const float*)d_in[13];
    const float* b2   = (const float*)d_in[14];
    float* out = (float*)d_out;

    cudaFuncSetAttribute(gemm_k<0>, cudaFuncAttributeMaxDynamicSharedMemorySize, GEMM_SMEM);
    cudaFuncSetAttribute(gemm_k<1>, cudaFuncAttributeMaxDynamicSharedMemorySize, GEMM_SMEM);
    cudaFuncSetAttribute(gemm_k<2>, cudaFuncAttributeMaxDynamicSharedMemorySize, GEMM_SMEM);
    cudaFuncSetAttribute(attn_ln2_kernel, cudaFuncAttributeMaxDynamicSharedMemorySize, ATTN_SMEM);

    prep_ln1_kernel<<<PREP_BLOCKS + LN1_BLOCKS, 256>>>(
        wq_w, wk_w, wv_w, wq_b, wk_b, wv_b, d1_w, d2_w, x, g1, b1);                 // 0
    gemm_k<0><<<dim3(NQKV / 128, TTOK / 128), 512, GEMM_SMEM>>>(nullptr, nullptr);  // 1
    attn_ln2_kernel<<<TTOK / 8, 256, ATTN_SMEM>>>(x, g2, b2);                       // 2
    gemm_k<1><<<dim3(HID / 128, TTOK / 128), 512, GEMM_SMEM>>>(d1_b, nullptr);      // 3
    gemm_k<2><<<dim3(DIMV / 128, TTOK / 128), 512, GEMM_SMEM>>>(d2_b, out);         // 4
}